// round 16
// baseline (speedup 1.0000x reference)
#include <cuda_runtime.h>
#include <cstdint>

// ---------------------------------------------------------------------------
// TrajectoryFK R16: 2-kernel pipeline.
//   A: TMA full-tile staged in 4 quarter-mbarriers (per-warp overlap) ->
//      warp scans -> block aggregate -> fused tail scan of 512 aggregates
//      (atomic counter, self-resetting).  Warms L2 for C.
//   C: 256 threads / 128 timesteps. Warps 0-3: element scan -> G (global
//      affine) + light FK subtrees. Warps 4-7: heavy FK subtree using G
//      passed through padded smem. TMA tile in, TMA bulk store out.
//
// affine element e_t = (M_t, u_t): M_t = rotmat(joint1 6d), u_t = M_t @ vel_t
// combine(a earlier, b later) = (a.M @ b.M, a.u + a.M @ b.u)
// ---------------------------------------------------------------------------

constexpr int L    = 65536;
constexpr int TPB  = 128;        // timesteps per block (A rows, C rows)
constexpr int NB   = L / TPB;    // 512 aggregates / blocks
constexpr int ROWF = 132;        // floats per timestep row (22*6)
constexpr unsigned QBYTES = 32 * ROWF * 4;    // one quarter tile (32 rows)

// kernel A shared layout (float indices)
constexpr int SA_ROW  = 0;                    // 128*132 staged rows
constexpr int SA_WAGG = TPB * ROWF;           // 16896: 4 warp aggs * 12
constexpr int SA_MBAR = SA_WAGG + 48;         // 16944: 4 mbarriers (8 floats)
constexpr int SMEM_A  = (SA_MBAR + 8) * 4;    // 67,808 B -> 3 blocks/SM

// kernel C shared layout (float indices)
constexpr int S_ROW  = 0;                     // 128*132 staged rows (reused as out tile)
constexpr int S_WAGG = TPB * ROWF;            // 16896: 4 warp aggs * 12
constexpr int S_OFF  = S_WAGG + 48;           // 16944: 66 offsets
constexpr int S_G    = S_OFF + 66;            // 17010: 128 * 13 (padded G)
constexpr int S_MBAR = S_G + 128 * 13;        // 18674 (even -> 8B aligned)
constexpr int SMEM_C = (S_MBAR + 2) * 4;      // 74,704 B -> 3 blocks/SM

__device__ float    g_agg[NB * 12];    // block aggregates
__device__ float    g_pref[NB * 12];   // exclusive block prefixes
__device__ unsigned g_cnt = 0;         // arrival counter (self-resetting)

// ---------------------------------------------------------------------------
__device__ __forceinline__ void d6_to_mat(const float* d, float* m) {
    float a1x = d[0], a1y = d[1], a1z = d[2];
    float a2x = d[3], a2y = d[4], a2z = d[5];
    float n1 = a1x * a1x + a1y * a1y + a1z * a1z;
    float i1 = rsqrtf(fmaxf(n1, 1e-24f));
    float b1x = a1x * i1, b1y = a1y * i1, b1z = a1z * i1;
    float dp = b1x * a2x + b1y * a2y + b1z * a2z;
    float c2x = a2x - b1x * dp, c2y = a2y - b1y * dp, c2z = a2z - b1z * dp;
    float n2 = c2x * c2x + c2y * c2y + c2z * c2z;
    float i2 = rsqrtf(fmaxf(n2, 1e-24f));
    float b2x = c2x * i2, b2y = c2y * i2, b2z = c2z * i2;
    float b3x = b1y * b2z - b1z * b2y;
    float b3y = b1z * b2x - b1x * b2z;
    float b3z = b1x * b2y - b1y * b2x;
    m[0] = b1x; m[1] = b2x; m[2] = b3x;
    m[3] = b1y; m[4] = b2y; m[5] = b3y;
    m[6] = b1z; m[7] = b2z; m[8] = b3z;
}

__device__ __forceinline__ void mat3mul(float* __restrict__ c,
                                        const float* a, const float* b) {
#pragma unroll
    for (int r = 0; r < 3; r++) {
        float a0 = a[r * 3], a1 = a[r * 3 + 1], a2 = a[r * 3 + 2];
#pragma unroll
        for (int k = 0; k < 3; k++)
            c[r * 3 + k] = a0 * b[k] + a1 * b[3 + k] + a2 * b[6 + k];
    }
}

// r = a ∘ b (a earlier); alias-safe
__device__ __forceinline__ void aff_combine(float* r, const float* a, const float* b) {
    float t[12];
#pragma unroll
    for (int rr = 0; rr < 3; rr++) {
        float a0 = a[rr * 3], a1 = a[rr * 3 + 1], a2 = a[rr * 3 + 2];
#pragma unroll
        for (int k = 0; k < 3; k++)
            t[rr * 3 + k] = a0 * b[k] + a1 * b[3 + k] + a2 * b[6 + k];
        t[9 + rr] = a[9 + rr] + a0 * b[9] + a1 * b[10] + a2 * b[11];
    }
#pragma unroll
    for (int i = 0; i < 12; i++) r[i] = t[i];
}

__device__ __forceinline__ void aff_identity(float* v) {
#pragma unroll
    for (int i = 0; i < 12; i++) v[i] = 0.0f;
    v[0] = v[4] = v[8] = 1.0f;
}

// build element from 12 leading floats of a row
__device__ __forceinline__ void build_from12(const float* q, float* val) {
    float d6[6] = {q[6], q[7], q[8], q[9], q[10], q[11]};
    d6_to_mat(d6, val);
    float vx = q[0], vy = q[1], vz = q[2];
    val[9]  = val[0] * vx + val[1] * vy + val[2] * vz;
    val[10] = val[3] * vx + val[4] * vy + val[5] * vz;
    val[11] = val[6] * vx + val[7] * vy + val[8] * vz;
}

// warp-ordered inclusive scan of affine elements
__device__ __forceinline__ void warp_incl_scan(float* val, int lane) {
#pragma unroll
    for (int off = 1; off < 32; off <<= 1) {
        float o[12];
#pragma unroll
        for (int i = 0; i < 12; i++)
            o[i] = __shfl_up_sync(0xffffffffu, val[i], off);
        if (lane >= off) aff_combine(val, o, val);
    }
}

// mbarrier wait, phase 0
__device__ __forceinline__ void mbar_wait0(uint32_t mbar) {
    unsigned done;
    asm volatile(
        "{\n\t.reg .pred p;\n\t"
        "mbarrier.try_wait.parity.acquire.cta.shared::cta.b64 p, [%1], 0;\n\t"
        "selp.b32 %0, 1, 0, p;\n\t}"
        : "=r"(done) : "r"(mbar) : "memory");
    while (!done) {
        asm volatile(
            "{\n\t.reg .pred p;\n\t"
            "mbarrier.try_wait.parity.acquire.cta.shared::cta.b64 p, [%1], 0, 0x989680;\n\t"
            "selp.b32 %0, 1, 0, p;\n\t}"
            : "=r"(done) : "r"(mbar) : "memory");
    }
}

__device__ __forceinline__ void mbar_init1(uint32_t mbar) {
    asm volatile("mbarrier.init.shared.b64 [%0], 1;" :: "r"(mbar) : "memory");
}

__device__ __forceinline__ void async_fence() {
    asm volatile("fence.proxy.async.shared::cta;" ::: "memory");
}

// issue bulk TMA load (mbar already inited & fenced)
__device__ __forceinline__ void tile_load_issue(uint32_t dst, const float* src,
                                                unsigned bytes, uint32_t mbar) {
    asm volatile("mbarrier.arrive.expect_tx.shared.b64 _, [%0], %1;"
                 :: "r"(mbar), "r"(bytes) : "memory");
    asm volatile(
        "cp.async.bulk.shared::cluster.global.mbarrier::complete_tx::bytes "
        "[%0], [%1], %2, [%3];"
        :: "r"(dst), "l"(src), "r"(bytes), "r"(mbar)
        : "memory");
}

// ---------------------------------------------------------------------------
// Kernel A: quartered TMA tile -> warp scans -> aggregate -> fused tail scan.
// ---------------------------------------------------------------------------
__global__ void __launch_bounds__(TPB)
kernelA(const float* __restrict__ pred) {
    extern __shared__ float smem[];
    float* s_row  = smem + SA_ROW;
    float* s_wagg = smem + SA_WAGG;
    __shared__ unsigned s_tail;
    __shared__ float s_b[4][12];
    __shared__ float s_bp[4][12];

    const int tid  = threadIdx.x;
    const int lane = tid & 31;
    const int warp = tid >> 5;
    const int b    = blockIdx.x;
    const size_t base = (size_t)b * TPB;

    uint32_t mb0  = (uint32_t)__cvta_generic_to_shared(smem + SA_MBAR);
    uint32_t srow = (uint32_t)__cvta_generic_to_shared(s_row);

    if (tid == 0) {
#pragma unroll
        for (int w = 0; w < 4; w++) mbar_init1(mb0 + 8 * w);
        async_fence();
    }
    __syncthreads();                       // init visible before any wait
    if (tid == 0) {
#pragma unroll
        for (int w = 0; w < 4; w++)
            tile_load_issue(srow + (unsigned)(32 * w * ROWF * 4),
                            pred + (base + 32 * w) * ROWF, QBYTES,
                            mb0 + 8 * w);
    }

    // each warp waits only for its own 32 rows
    mbar_wait0(mb0 + 8 * warp);

    float val[12];
    build_from12(s_row + tid * ROWF, val);
    warp_incl_scan(val, lane);

    if (lane == 31) {
#pragma unroll
        for (int i = 0; i < 12; i++) s_wagg[warp * 12 + i] = val[i];
    }
    __syncthreads();

    if (tid == 0) {
        float agg[12];
#pragma unroll
        for (int i = 0; i < 12; i++) agg[i] = s_wagg[i];
        aff_combine(agg, agg, s_wagg + 12);
        aff_combine(agg, agg, s_wagg + 24);
        aff_combine(agg, agg, s_wagg + 36);
#pragma unroll
        for (int i = 0; i < 12; i++) g_agg[b * 12 + i] = agg[i];
        __threadfence();
        unsigned old = atomicAdd(&g_cnt, 1u);
        s_tail = (old == NB - 1) ? 1u : 0u;
    }
    __syncthreads();
    if (s_tail == 0) return;

    // ---- tail block: scan 512 aggregates -> exclusive prefixes -------------
    __threadfence();   // make all g_agg writes visible

    // thread t handles aggregates 4t..4t+3
    float q0[12], q1[12], q2[12], q3[12];
#pragma unroll
    for (int i = 0; i < 12; i++) q0[i] = g_agg[(4 * tid + 0) * 12 + i];
#pragma unroll
    for (int i = 0; i < 12; i++) q1[i] = g_agg[(4 * tid + 1) * 12 + i];
#pragma unroll
    for (int i = 0; i < 12; i++) q2[i] = g_agg[(4 * tid + 2) * 12 + i];
#pragma unroll
    for (int i = 0; i < 12; i++) q3[i] = g_agg[(4 * tid + 3) * 12 + i];

    float c[12];
#pragma unroll
    for (int i = 0; i < 12; i++) c[i] = q0[i];
    aff_combine(c, c, q1);
    aff_combine(c, c, q2);
    aff_combine(c, c, q3);

    float inc[12];
#pragma unroll
    for (int i = 0; i < 12; i++) inc[i] = c[i];
    warp_incl_scan(inc, lane);

    if (lane == 31) {
#pragma unroll
        for (int i = 0; i < 12; i++) s_b[warp][i] = inc[i];
    }
    __syncthreads();
    if (warp == 0 && lane < 4) {
        float w[12];
#pragma unroll
        for (int i = 0; i < 12; i++) w[i] = s_b[lane][i];
#pragma unroll
        for (int off = 1; off < 4; off <<= 1) {
            float o[12];
#pragma unroll
            for (int i = 0; i < 12; i++)
                o[i] = __shfl_up_sync(0x0000000fu, w[i], off);
            if (lane >= off) aff_combine(w, o, w);
        }
        float ex[12];
#pragma unroll
        for (int i = 0; i < 12; i++)
            ex[i] = __shfl_up_sync(0x0000000fu, w[i], 1);
        if (lane == 0) aff_identity(ex);
#pragma unroll
        for (int i = 0; i < 12; i++) s_bp[lane][i] = ex[i];
    }
    __syncthreads();

    float et[12];
#pragma unroll
    for (int i = 0; i < 12; i++)
        et[i] = __shfl_up_sync(0xffffffffu, inc[i], 1);
    float excl[12];
#pragma unroll
    for (int i = 0; i < 12; i++) excl[i] = s_bp[warp][i];
    if (lane > 0) aff_combine(excl, excl, et);

#pragma unroll
    for (int i = 0; i < 12; i++) g_pref[(4 * tid + 0) * 12 + i] = excl[i];
    aff_combine(excl, excl, q0);
#pragma unroll
    for (int i = 0; i < 12; i++) g_pref[(4 * tid + 1) * 12 + i] = excl[i];
    aff_combine(excl, excl, q1);
#pragma unroll
    for (int i = 0; i < 12; i++) g_pref[(4 * tid + 2) * 12 + i] = excl[i];
    aff_combine(excl, excl, q2);
#pragma unroll
    for (int i = 0; i < 12; i++) g_pref[(4 * tid + 3) * 12 + i] = excl[i];

    __syncthreads();
    if (tid == 0) g_cnt = 0;             // reset for next graph replay
}

// ---------------------------------------------------------------------------
// Kernel C: 256 threads, split FK.
// ---------------------------------------------------------------------------
__device__ __forceinline__ void fk_rot(float* Rc, const float* Rp,
                                       const float* r, int j) {
    float d6[6];
#pragma unroll
    for (int i = 0; i < 6; i++) d6[i] = r[6 * j + i];
    float M[9];
    d6_to_mat(d6, M);
    mat3mul(Rc, Rp, M);
}

__device__ __forceinline__ void fk_pos(float* pc, const float* pp, const float* Rp,
                                       const float* s_off, int j) {
    float ox = s_off[j * 3], oy = s_off[j * 3 + 1], oz = s_off[j * 3 + 2];
    pc[0] = pp[0] + Rp[0] * ox + Rp[1] * oy + Rp[2] * oz;
    pc[1] = pp[1] + Rp[3] * ox + Rp[4] * oy + Rp[5] * oz;
    pc[2] = pp[2] + Rp[6] * ox + Rp[7] * oy + Rp[8] * oz;
}

extern "C" __global__ void __launch_bounds__(256, 3)
kernelC(const float* __restrict__ pred, const float* __restrict__ offs,
        float* __restrict__ out) {
    extern __shared__ float smem[];
    float* s_row  = smem + S_ROW;
    float* s_wagg = smem + S_WAGG;
    float* s_off  = smem + S_OFF;
    float* s_G    = smem + S_G;

    const int tid  = threadIdx.x;
    const int lane = tid & 31;
    const int warp = tid >> 5;
    const int b    = blockIdx.x;
    const size_t base = (size_t)b * TPB;
    const bool scanhalf = (tid < TPB);
    const int t = scanhalf ? tid : (tid - TPB);

    uint32_t mbar = (uint32_t)__cvta_generic_to_shared(smem + S_MBAR);
    uint32_t srow = (uint32_t)__cvta_generic_to_shared(s_row);

    if (tid == 0) { mbar_init1(mbar); async_fence(); }
    __syncthreads();                       // init visible before any wait
    if (tid == 0)
        tile_load_issue(srow, pred + base * ROWF,
                        (unsigned)(TPB * ROWF * 4), mbar);
    if (tid < 66) s_off[tid] = offs[tid];

    // ---- scan half: build element from gmem (L2-warm from A), scan ---------
    float G[12];
    float val[12];
    if (scanhalf) {
        const float4* r4 = (const float4*)(pred + (base + t) * ROWF);
        float4 q0 = __ldg(r4), q1 = __ldg(r4 + 1), q2 = __ldg(r4 + 2);
        float q[12] = {q0.x, q0.y, q0.z, q0.w, q1.x, q1.y, q1.z, q1.w,
                       q2.x, q2.y, q2.z, q2.w};
        build_from12(q, val);
        warp_incl_scan(val, lane);
        if (lane == 31) {
#pragma unroll
            for (int i = 0; i < 12; i++) s_wagg[warp * 12 + i] = val[i];
        }
    }
    __syncthreads();

    if (scanhalf) {
        float pre[12];
        aff_identity(pre);
        for (int w = 0; w < warp; w++) aff_combine(pre, pre, s_wagg + w * 12);
        float linc[12];
        aff_combine(linc, pre, val);
        float P[12];
#pragma unroll
        for (int i = 0; i < 12; i++) P[i] = __ldg(&g_pref[b * 12 + i]);
        aff_combine(G, P, linc);
#pragma unroll
        for (int i = 0; i < 12; i++) s_G[t * 13 + i] = G[i];
    }
    __syncthreads();                       // s_G visible to FK half
    if (!scanhalf) {
#pragma unroll
        for (int i = 0; i < 12; i++) G[i] = s_G[t * 13 + i];
    }

    // ---- wait for TMA row staging ------------------------------------------
    mbar_wait0(mbar);

    // ---- split FK ----------------------------------------------------------
    const float* r = s_row + t * ROWF;
    const float* R = G;
    float pos0[3] = {G[9], G[10], G[11]};

    float po0[27];   // scan half outputs
    float po1[39];   // fk half outputs

    if (scanhalf) {
        // joints {0,1,2,4,5,7,8,10,11}
#define EM0(k, p) { po0[3*(k)] = (p)[0]; po0[3*(k)+1] = (p)[1]; po0[3*(k)+2] = (p)[2]; }
        EM0(0, pos0);
        float pos1[3]; fk_pos(pos1, pos0, R, s_off, 1);   EM0(1, pos1);
        float R2[9];  fk_rot(R2, R, r, 2);
        float pos2[3]; fk_pos(pos2, pos0, R, s_off, 2);   EM0(2, pos2);
        float R4[9];  fk_rot(R4, R, r, 4);
        float pos4[3]; fk_pos(pos4, pos1, R, s_off, 4);   EM0(3, pos4);
        float R5[9];  fk_rot(R5, R2, r, 5);
        float pos5[3]; fk_pos(pos5, pos2, R2, s_off, 5);  EM0(4, pos5);
        float R7[9];  fk_rot(R7, R4, r, 7);
        float pos7[3]; fk_pos(pos7, pos4, R4, s_off, 7);  EM0(5, pos7);
        float R8[9];  fk_rot(R8, R5, r, 8);
        float pos8[3]; fk_pos(pos8, pos5, R5, s_off, 8);  EM0(6, pos8);
        float pos10[3]; fk_pos(pos10, pos7, R7, s_off, 10); EM0(7, pos10);
        float pos11[3]; fk_pos(pos11, pos8, R8, s_off, 11); EM0(8, pos11);
#undef EM0
    } else {
        // joints {3,6,9,12,13,14,15,16,17,18,19,20,21}
#define EM1(k, p) { po1[3*(k)] = (p)[0]; po1[3*(k)+1] = (p)[1]; po1[3*(k)+2] = (p)[2]; }
        float R3[9];  fk_rot(R3, R, r, 3);
        float pos3[3]; fk_pos(pos3, pos0, R, s_off, 3);   EM1(0, pos3);
        float R6[9];  fk_rot(R6, R3, r, 6);
        float pos6[3]; fk_pos(pos6, pos3, R3, s_off, 6);  EM1(1, pos6);
        float R9[9];  fk_rot(R9, R6, r, 9);
        float pos9[3]; fk_pos(pos9, pos6, R6, s_off, 9);  EM1(2, pos9);
        float R12[9]; fk_rot(R12, R9, r, 12);
        float pos12[3]; fk_pos(pos12, pos9, R9, s_off, 12); EM1(3, pos12);
        float R13[9]; fk_rot(R13, R9, r, 13);
        float pos13[3]; fk_pos(pos13, pos9, R9, s_off, 13); EM1(4, pos13);
        float R14[9]; fk_rot(R14, R9, r, 14);
        float pos14[3]; fk_pos(pos14, pos9, R9, s_off, 14); EM1(5, pos14);
        float pos15[3]; fk_pos(pos15, pos12, R12, s_off, 15); EM1(6, pos15);
        float R16[9]; fk_rot(R16, R13, r, 16);
        float pos16[3]; fk_pos(pos16, pos13, R13, s_off, 16); EM1(7, pos16);
        float R17[9]; fk_rot(R17, R14, r, 17);
        float pos17[3]; fk_pos(pos17, pos14, R14, s_off, 17); EM1(8, pos17);
        float R18[9]; fk_rot(R18, R16, r, 18);
        float pos18[3]; fk_pos(pos18, pos16, R16, s_off, 18); EM1(9, pos18);
        float R19[9]; fk_rot(R19, R17, r, 19);
        float pos19[3]; fk_pos(pos19, pos17, R17, s_off, 19); EM1(10, pos19);
        float pos20[3]; fk_pos(pos20, pos18, R18, s_off, 20); EM1(11, pos20);
        float pos21[3]; fk_pos(pos21, pos19, R19, s_off, 21); EM1(12, pos21);
#undef EM1
    }

    // ---- all row reads done: reuse s_row region as the output tile ---------
    __syncthreads();
    float* o = s_row + t * 66;
    if (scanhalf) {
        // J0 = {0,1,2,4,5,7,8,10,11}
#pragma unroll
        for (int i = 0; i < 3; i++) {
            o[0 + i]  = po0[0 + i];    // j0
            o[3 + i]  = po0[3 + i];    // j1
            o[6 + i]  = po0[6 + i];    // j2
            o[12 + i] = po0[9 + i];    // j4
            o[15 + i] = po0[12 + i];   // j5
            o[21 + i] = po0[15 + i];   // j7
            o[24 + i] = po0[18 + i];   // j8
            o[30 + i] = po0[21 + i];   // j10
            o[33 + i] = po0[24 + i];   // j11
        }
    } else {
        // J1 = {3,6,9,12,13,14,15,16,17,18,19,20,21}
#pragma unroll
        for (int i = 0; i < 3; i++) {
            o[9 + i]  = po1[0 + i];    // j3
            o[18 + i] = po1[3 + i];    // j6
            o[27 + i] = po1[6 + i];    // j9
            o[36 + i] = po1[9 + i];    // j12
            o[39 + i] = po1[12 + i];   // j13
            o[42 + i] = po1[15 + i];   // j14
            o[45 + i] = po1[18 + i];   // j15
            o[48 + i] = po1[21 + i];   // j16
            o[51 + i] = po1[24 + i];   // j17
            o[54 + i] = po1[27 + i];   // j18
            o[57 + i] = po1[30 + i];   // j19
            o[60 + i] = po1[33 + i];   // j20
            o[63 + i] = po1[36 + i];   // j21
        }
    }
    __syncthreads();

    if (tid == 0) {
        uint32_t sout = (uint32_t)__cvta_generic_to_shared(s_row);
        asm volatile("fence.proxy.async.shared::cta;" ::: "memory");
        asm volatile(
            "cp.async.bulk.global.shared::cta.bulk_group [%0], [%1], %2;"
            :: "l"(out + base * 66), "r"(sout),
               "r"((unsigned)(TPB * 66 * 4)) : "memory");
        asm volatile("cp.async.bulk.commit_group;" ::: "memory");
        asm volatile("cp.async.bulk.wait_group 0;" ::: "memory");
    }
    __syncthreads();
}

// ---------------------------------------------------------------------------
extern "C" void kernel_launch(void* const* d_in, const int* in_sizes, int n_in,
                              void* d_out, int out_size) {
    const float* pred = (const float*)d_in[0];   // (65536, 22, 6) f32
    const float* offs = (const float*)d_in[1];   // (22, 3) f32
    float* out = (float*)d_out;                  // (65536, 22, 3) f32

    cudaFuncSetAttribute(kernelA, cudaFuncAttributeMaxDynamicSharedMemorySize,
                         SMEM_A);
    cudaFuncSetAttribute(kernelC, cudaFuncAttributeMaxDynamicSharedMemorySize,
                         SMEM_C);
    kernelA<<<NB, TPB, SMEM_A>>>(pred);
    kernelC<<<NB, 256, SMEM_C>>>(pred, offs, out);
}

// round 17
// speedup vs baseline: 1.7181x; 1.7181x over previous
#include <cuda_runtime.h>
#include <cstdint>

// ---------------------------------------------------------------------------
// TrajectoryFK R17 = R15 (best, 24.6us) minus L2-prefetch, plus quartered
// TMA waits in kernel C.
//   AB: strided-LDG aggregate build (48B/row) over 128 blocks + fused
//       tail-scan of 512 aggregates (atomic counter, self-resetting).
//   C:  TMA tile staged as 4 quarters (per-warp mbarrier wait) + in-block
//       rescan + FK (outputs in regs) + smem-reuse output tile + TMA store.
//
// affine element e_t = (M_t, u_t): M_t = rotmat(joint1 6d), u_t = M_t @ vel_t
// combine(a earlier, b later) = (a.M @ b.M, a.u + a.M @ b.u)
// ---------------------------------------------------------------------------

constexpr int L    = 65536;
constexpr int TPB  = 128;        // timesteps per C block / per aggregate
constexpr int NB   = L / TPB;    // 512 aggregates / C blocks
constexpr int ROWF = 132;        // floats per timestep row (22*6)
constexpr unsigned QBYTES = 32 * ROWF * 4;   // one quarter tile (32 rows)

// kernel AB config: 128 blocks x 256 threads; block covers 4 aggregates
constexpr int AB_TPB   = 256;
constexpr int AB_GRID  = NB / 4;           // 128
constexpr int AB_ROWS  = 4 * TPB;          // 512 rows per block

// kernel C shared layout (float indices)
constexpr int S_ROW  = 0;                     // 128*132 staged rows (reused as out tile)
constexpr int S_WAGG = TPB * ROWF;            // 16896: 4 warp aggs * 12
constexpr int S_OFF  = S_WAGG + 48;           // 16944: 66 offsets
constexpr int S_MBAR = S_OFF + 66;            // 17010 (even -> 8B aligned), 4 mbarriers
constexpr int SMEM_C = (S_MBAR + 8) * 4;      // 68,072 B -> 3 blocks/SM

__device__ float    g_agg[NB * 12];    // block aggregates
__device__ float    g_pref[NB * 12];   // exclusive block prefixes
__device__ unsigned g_cnt = 0;         // arrival counter (self-resetting)

// ---------------------------------------------------------------------------
__device__ __forceinline__ void d6_to_mat(const float* d, float* m) {
    float a1x = d[0], a1y = d[1], a1z = d[2];
    float a2x = d[3], a2y = d[4], a2z = d[5];
    float n1 = a1x * a1x + a1y * a1y + a1z * a1z;
    float i1 = rsqrtf(fmaxf(n1, 1e-24f));
    float b1x = a1x * i1, b1y = a1y * i1, b1z = a1z * i1;
    float dp = b1x * a2x + b1y * a2y + b1z * a2z;
    float c2x = a2x - b1x * dp, c2y = a2y - b1y * dp, c2z = a2z - b1z * dp;
    float n2 = c2x * c2x + c2y * c2y + c2z * c2z;
    float i2 = rsqrtf(fmaxf(n2, 1e-24f));
    float b2x = c2x * i2, b2y = c2y * i2, b2z = c2z * i2;
    float b3x = b1y * b2z - b1z * b2y;
    float b3y = b1z * b2x - b1x * b2z;
    float b3z = b1x * b2y - b1y * b2x;
    m[0] = b1x; m[1] = b2x; m[2] = b3x;
    m[3] = b1y; m[4] = b2y; m[5] = b3y;
    m[6] = b1z; m[7] = b2z; m[8] = b3z;
}

__device__ __forceinline__ void mat3mul(float* __restrict__ c,
                                        const float* a, const float* b) {
#pragma unroll
    for (int r = 0; r < 3; r++) {
        float a0 = a[r * 3], a1 = a[r * 3 + 1], a2 = a[r * 3 + 2];
#pragma unroll
        for (int k = 0; k < 3; k++)
            c[r * 3 + k] = a0 * b[k] + a1 * b[3 + k] + a2 * b[6 + k];
    }
}

// r = a ∘ b (a earlier); alias-safe
__device__ __forceinline__ void aff_combine(float* r, const float* a, const float* b) {
    float t[12];
#pragma unroll
    for (int rr = 0; rr < 3; rr++) {
        float a0 = a[rr * 3], a1 = a[rr * 3 + 1], a2 = a[rr * 3 + 2];
#pragma unroll
        for (int k = 0; k < 3; k++)
            t[rr * 3 + k] = a0 * b[k] + a1 * b[3 + k] + a2 * b[6 + k];
        t[9 + rr] = a[9 + rr] + a0 * b[9] + a1 * b[10] + a2 * b[11];
    }
#pragma unroll
    for (int i = 0; i < 12; i++) r[i] = t[i];
}

__device__ __forceinline__ void aff_identity(float* v) {
#pragma unroll
    for (int i = 0; i < 12; i++) v[i] = 0.0f;
    v[0] = v[4] = v[8] = 1.0f;
}

// build element from 12 leading floats of a row
__device__ __forceinline__ void build_from12(const float* q, float* val) {
    float d6[6] = {q[6], q[7], q[8], q[9], q[10], q[11]};
    d6_to_mat(d6, val);
    float vx = q[0], vy = q[1], vz = q[2];
    val[9]  = val[0] * vx + val[1] * vy + val[2] * vz;
    val[10] = val[3] * vx + val[4] * vy + val[5] * vz;
    val[11] = val[6] * vx + val[7] * vy + val[8] * vz;
}

// warp-ordered inclusive scan of affine elements
__device__ __forceinline__ void warp_incl_scan(float* val, int lane) {
#pragma unroll
    for (int off = 1; off < 32; off <<= 1) {
        float o[12];
#pragma unroll
        for (int i = 0; i < 12; i++)
            o[i] = __shfl_up_sync(0xffffffffu, val[i], off);
        if (lane >= off) aff_combine(val, o, val);
    }
}

// mbarrier wait, phase 0
__device__ __forceinline__ void mbar_wait0(uint32_t mbar) {
    unsigned done;
    asm volatile(
        "{\n\t.reg .pred p;\n\t"
        "mbarrier.try_wait.parity.acquire.cta.shared::cta.b64 p, [%1], 0;\n\t"
        "selp.b32 %0, 1, 0, p;\n\t}"
        : "=r"(done) : "r"(mbar) : "memory");
    while (!done) {
        asm volatile(
            "{\n\t.reg .pred p;\n\t"
            "mbarrier.try_wait.parity.acquire.cta.shared::cta.b64 p, [%1], 0, 0x989680;\n\t"
            "selp.b32 %0, 1, 0, p;\n\t}"
            : "=r"(done) : "r"(mbar) : "memory");
    }
}

__device__ __forceinline__ void mbar_init1(uint32_t mbar) {
    asm volatile("mbarrier.init.shared.b64 [%0], 1;" :: "r"(mbar) : "memory");
}

__device__ __forceinline__ void async_fence() {
    asm volatile("fence.proxy.async.shared::cta;" ::: "memory");
}

// issue bulk TMA load (mbar already inited & fenced)
__device__ __forceinline__ void tile_load_issue(uint32_t dst, const float* src,
                                                unsigned bytes, uint32_t mbar) {
    asm volatile("mbarrier.arrive.expect_tx.shared.b64 _, [%0], %1;"
                 :: "r"(mbar), "r"(bytes) : "memory");
    asm volatile(
        "cp.async.bulk.shared::cluster.global.mbarrier::complete_tx::bytes "
        "[%0], [%1], %2, [%3];"
        :: "r"(dst), "l"(src), "r"(bytes), "r"(mbar)
        : "memory");
}

// ---------------------------------------------------------------------------
// Kernel AB: aggregates + fused tail scan-of-aggregates (NO prefetch).
//   block b covers rows [512b, 512b+512) = aggregates [4b, 4b+4).
//   warp w (0..7): pair p = w>>1 -> aggregate 4b+p; half h = w&1.
//   thread: rows r0 = 512b + p*128 + h*64 + lane*2, r0+1 (serial combine).
// ---------------------------------------------------------------------------
__global__ void __launch_bounds__(AB_TPB)
kernelAB(const float* __restrict__ pred) {
    __shared__ float s_wagg[8][12];
    __shared__ unsigned s_tail;

    const int tid  = threadIdx.x;
    const int lane = tid & 31;
    const int warp = tid >> 5;
    const int b    = blockIdx.x;
    const size_t rowbase = (size_t)b * AB_ROWS;

    // strided loads: only floats 0..11 of each row (3 x float4, 2 rows)
    const size_t r0 = rowbase + (size_t)(warp >> 1) * 128 + (warp & 1) * 64
                    + lane * 2;
    const float4* p0 = (const float4*)(pred + r0 * ROWF);
    const float4* p1 = (const float4*)(pred + (r0 + 1) * ROWF);
    float4 a0 = __ldg(p0), a1 = __ldg(p0 + 1), a2 = __ldg(p0 + 2);
    float4 b0 = __ldg(p1), b1 = __ldg(p1 + 1), b2 = __ldg(p1 + 2);

    float val[12], e[12];
    {
        float qa[12] = {a0.x, a0.y, a0.z, a0.w, a1.x, a1.y, a1.z, a1.w,
                        a2.x, a2.y, a2.z, a2.w};
        build_from12(qa, val);
        float qb[12] = {b0.x, b0.y, b0.z, b0.w, b1.x, b1.y, b1.z, b1.w,
                        b2.x, b2.y, b2.z, b2.w};
        build_from12(qb, e);
        aff_combine(val, val, e);
    }
    warp_incl_scan(val, lane);

    if (lane == 31) {
#pragma unroll
        for (int i = 0; i < 12; i++) s_wagg[warp][i] = val[i];
    }
    __syncthreads();

    // aggregate 4b+t = halfA ∘ halfB  (t = 0..3)
    if (tid < 4) {
        float agg[12];
#pragma unroll
        for (int i = 0; i < 12; i++) agg[i] = s_wagg[2 * tid][i];
        aff_combine(agg, agg, s_wagg[2 * tid + 1]);
#pragma unroll
        for (int i = 0; i < 12; i++) g_agg[(4 * b + tid) * 12 + i] = agg[i];
    }
    __syncthreads();

    // arrival counter; last block performs the aggregate scan (old kernel B)
    if (tid == 0) {
        __threadfence();
        unsigned old = atomicAdd(&g_cnt, 1u);
        s_tail = (old == AB_GRID - 1) ? 1u : 0u;
    }
    __syncthreads();
    if (s_tail == 0) return;

    // ---- tail block: scan 512 aggregates -> exclusive prefixes -------------
    __threadfence();   // acquire side: make all g_agg writes visible

    // thread t handles aggregates 2t, 2t+1
    float pa[12], pb[12];
#pragma unroll
    for (int i = 0; i < 12; i++) pa[i] = g_agg[(2 * tid) * 12 + i];
#pragma unroll
    for (int i = 0; i < 12; i++) pb[i] = g_agg[(2 * tid + 1) * 12 + i];

    float inc[12];
#pragma unroll
    for (int i = 0; i < 12; i++) inc[i] = pa[i];
    aff_combine(inc, inc, pb);
    warp_incl_scan(inc, lane);           // inclusive over pairs within warp

    __shared__ float s_b[8][12];
    __shared__ float s_bp[8][12];
    if (lane == 31) {
#pragma unroll
        for (int i = 0; i < 12; i++) s_b[warp][i] = inc[i];
    }
    __syncthreads();
    if (warp == 0 && lane < 8) {
        float w[12];
#pragma unroll
        for (int i = 0; i < 12; i++) w[i] = s_b[lane][i];
#pragma unroll
        for (int off = 1; off < 8; off <<= 1) {
            float o[12];
#pragma unroll
            for (int i = 0; i < 12; i++)
                o[i] = __shfl_up_sync(0x000000ffu, w[i], off);
            if (lane >= off) aff_combine(w, o, w);
        }
        float ex[12];
#pragma unroll
        for (int i = 0; i < 12; i++)
            ex[i] = __shfl_up_sync(0x000000ffu, w[i], 1);
        if (lane == 0) aff_identity(ex);
#pragma unroll
        for (int i = 0; i < 12; i++) s_bp[lane][i] = ex[i];
    }
    __syncthreads();

    // exclusive prefix before pair t: W_warp ∘ (incl of pairs < t in warp)
    float et[12];
#pragma unroll
    for (int i = 0; i < 12; i++)
        et[i] = __shfl_up_sync(0xffffffffu, inc[i], 1);
    float excl[12];
#pragma unroll
    for (int i = 0; i < 12; i++) excl[i] = s_bp[warp][i];
    if (lane > 0) aff_combine(excl, excl, et);

    // g_pref[2t] = excl ; g_pref[2t+1] = excl ∘ a(2t)
#pragma unroll
    for (int i = 0; i < 12; i++) g_pref[(2 * tid) * 12 + i] = excl[i];
    aff_combine(excl, excl, pa);
#pragma unroll
    for (int i = 0; i < 12; i++) g_pref[(2 * tid + 1) * 12 + i] = excl[i];

    __syncthreads();
    if (tid == 0) g_cnt = 0;             // reset for next graph replay
}

// ---------------------------------------------------------------------------
// Kernel C: quartered TMA + rescan + FK (R12/R15-proven shape)
// ---------------------------------------------------------------------------
__device__ __forceinline__ void fk_rot(float* Rc, const float* Rp,
                                       const float* r, int j) {
    float d6[6];
#pragma unroll
    for (int i = 0; i < 6; i++) d6[i] = r[6 * j + i];
    float M[9];
    d6_to_mat(d6, M);
    mat3mul(Rc, Rp, M);
}

__device__ __forceinline__ void fk_pos(float* pc, const float* pp, const float* Rp,
                                       const float* s_off, int j) {
    float ox = s_off[j * 3], oy = s_off[j * 3 + 1], oz = s_off[j * 3 + 2];
    pc[0] = pp[0] + Rp[0] * ox + Rp[1] * oy + Rp[2] * oz;
    pc[1] = pp[1] + Rp[3] * ox + Rp[4] * oy + Rp[5] * oz;
    pc[2] = pp[2] + Rp[6] * ox + Rp[7] * oy + Rp[8] * oz;
}

extern "C" __global__ void __launch_bounds__(TPB)
kernelC(const float* __restrict__ pred, const float* __restrict__ offs,
        float* __restrict__ out) {
    extern __shared__ float smem[];
    float* s_row  = smem + S_ROW;
    float* s_wagg = smem + S_WAGG;
    float* s_off  = smem + S_OFF;

    const int tid  = threadIdx.x;
    const int lane = tid & 31;
    const int warp = tid >> 5;
    const int b    = blockIdx.x;
    const size_t base = (size_t)b * TPB;

    uint32_t mb0  = (uint32_t)__cvta_generic_to_shared(smem + S_MBAR);
    uint32_t srow = (uint32_t)__cvta_generic_to_shared(s_row);

    if (tid == 0) {
#pragma unroll
        for (int w = 0; w < 4; w++) mbar_init1(mb0 + 8 * w);
        async_fence();
    }
    __syncthreads();                       // init visible before any wait
    if (tid == 0) {
#pragma unroll
        for (int w = 0; w < 4; w++)
            tile_load_issue(srow + (unsigned)(32 * w * ROWF * 4),
                            pred + (base + 32 * w) * ROWF, QBYTES,
                            mb0 + 8 * w);
    }
    if (tid < 66) s_off[tid] = offs[tid];

    // ---- build element from gmem (overlaps TMA) ----------------------------
    float val[12];
    {
        const float4* r4 = (const float4*)(pred + (base + tid) * ROWF);
        float4 q0 = __ldg(r4), q1 = __ldg(r4 + 1), q2 = __ldg(r4 + 2);
        float q[12] = {q0.x, q0.y, q0.z, q0.w, q1.x, q1.y, q1.z, q1.w,
                       q2.x, q2.y, q2.z, q2.w};
        build_from12(q, val);
    }
    warp_incl_scan(val, lane);

    if (lane == 31) {
#pragma unroll
        for (int i = 0; i < 12; i++) s_wagg[warp * 12 + i] = val[i];
    }
    __syncthreads();

    float pre[12];
    aff_identity(pre);
    for (int w = 0; w < warp; w++) aff_combine(pre, pre, s_wagg + w * 12);
    float linc[12];
    aff_combine(linc, pre, val);

    float P[12];
#pragma unroll
    for (int i = 0; i < 12; i++) P[i] = __ldg(&g_pref[b * 12 + i]);
    float G[12];
    aff_combine(G, P, linc);

    // ---- wait only for THIS warp's quarter of the tile ---------------------
    mbar_wait0(mb0 + 8 * warp);

    // ---- FK tree: read smem rows, accumulate 66 outputs in REGISTERS -------
    const float* r = s_row + tid * ROWF;
    float po[66];
#define EMIT(j, p) { po[3*(j)] = (p)[0]; po[3*(j)+1] = (p)[1]; po[3*(j)+2] = (p)[2]; }

    const float* R = G;
    float pos0[3] = {G[9], G[10], G[11]};
    EMIT(0, pos0);
    float pos1[3]; fk_pos(pos1, pos0, R, s_off, 1);  EMIT(1, pos1);

    // chain 1 -> 4 -> 7 -> 10
    float R4[9];  fk_rot(R4, R, r, 4);
    float pos4[3];  fk_pos(pos4, pos1, R, s_off, 4);   EMIT(4, pos4);
    float R7[9];  fk_rot(R7, R4, r, 7);
    float pos7[3];  fk_pos(pos7, pos4, R4, s_off, 7);  EMIT(7, pos7);
    float pos10[3]; fk_pos(pos10, pos7, R7, s_off, 10); EMIT(10, pos10);

    // chain 0 -> 2 -> 5 -> 8 -> 11
    float R2[9];  fk_rot(R2, R, r, 2);
    float pos2[3];  fk_pos(pos2, pos0, R, s_off, 2);   EMIT(2, pos2);
    float R5[9];  fk_rot(R5, R2, r, 5);
    float pos5[3];  fk_pos(pos5, pos2, R2, s_off, 5);  EMIT(5, pos5);
    float R8[9];  fk_rot(R8, R5, r, 8);
    float pos8[3];  fk_pos(pos8, pos5, R5, s_off, 8);  EMIT(8, pos8);
    float pos11[3]; fk_pos(pos11, pos8, R8, s_off, 11); EMIT(11, pos11);

    // chain 0 -> 3 -> 6 -> 9
    float R3[9];  fk_rot(R3, R, r, 3);
    float pos3[3];  fk_pos(pos3, pos0, R, s_off, 3);   EMIT(3, pos3);
    float R6[9];  fk_rot(R6, R3, r, 6);
    float pos6[3];  fk_pos(pos6, pos3, R3, s_off, 6);  EMIT(6, pos6);
    float R9[9];  fk_rot(R9, R6, r, 9);
    float pos9[3];  fk_pos(pos9, pos6, R6, s_off, 9);  EMIT(9, pos9);

    // 9 -> 12 -> 15
    float R12[9]; fk_rot(R12, R9, r, 12);
    float pos12[3]; fk_pos(pos12, pos9, R9, s_off, 12); EMIT(12, pos12);
    float pos15[3]; fk_pos(pos15, pos12, R12, s_off, 15); EMIT(15, pos15);

    // 9 -> 13 -> 16 -> 18 -> 20
    float R13[9]; fk_rot(R13, R9, r, 13);
    float pos13[3]; fk_pos(pos13, pos9, R9, s_off, 13); EMIT(13, pos13);
    float R16[9]; fk_rot(R16, R13, r, 16);
    float pos16[3]; fk_pos(pos16, pos13, R13, s_off, 16); EMIT(16, pos16);
    float R18[9]; fk_rot(R18, R16, r, 18);
    float pos18[3]; fk_pos(pos18, pos16, R16, s_off, 18); EMIT(18, pos18);
    float pos20[3]; fk_pos(pos20, pos18, R18, s_off, 20); EMIT(20, pos20);

    // 9 -> 14 -> 17 -> 19 -> 21
    float R14[9]; fk_rot(R14, R9, r, 14);
    float pos14[3]; fk_pos(pos14, pos9, R9, s_off, 14); EMIT(14, pos14);
    float R17[9]; fk_rot(R17, R14, r, 17);
    float pos17[3]; fk_pos(pos17, pos14, R14, s_off, 17); EMIT(17, pos17);
    float R19[9]; fk_rot(R19, R17, r, 19);
    float pos19[3]; fk_pos(pos19, pos17, R17, s_off, 19); EMIT(19, pos19);
    float pos21[3]; fk_pos(pos21, pos19, R19, s_off, 21); EMIT(21, pos21);
#undef EMIT

    // ---- all row reads done: reuse s_row region as the output tile ---------
    __syncthreads();
    float* s_out = s_row;                 // 128*66 floats, contiguous
    {
        float2* o2 = (float2*)(s_out + tid * 66);
#pragma unroll
        for (int i = 0; i < 33; i++)
            o2[i] = make_float2(po[2 * i], po[2 * i + 1]);
    }
    __syncthreads();

    if (tid == 0) {
        uint32_t sout = (uint32_t)__cvta_generic_to_shared(s_out);
        asm volatile("fence.proxy.async.shared::cta;" ::: "memory");
        asm volatile(
            "cp.async.bulk.global.shared::cta.bulk_group [%0], [%1], %2;"
            :: "l"(out + base * 66), "r"(sout),
               "r"((unsigned)(TPB * 66 * 4)) : "memory");
        asm volatile("cp.async.bulk.commit_group;" ::: "memory");
        asm volatile("cp.async.bulk.wait_group 0;" ::: "memory");
    }
    __syncthreads();
}

// ---------------------------------------------------------------------------
extern "C" void kernel_launch(void* const* d_in, const int* in_sizes, int n_in,
                              void* d_out, int out_size) {
    const float* pred = (const float*)d_in[0];   // (65536, 22, 6) f32
    const float* offs = (const float*)d_in[1];   // (22, 3) f32
    float* out = (float*)d_out;                  // (65536, 22, 3) f32

    cudaFuncSetAttribute(kernelC, cudaFuncAttributeMaxDynamicSharedMemorySize,
                         SMEM_C);
    kernelAB<<<AB_GRID, AB_TPB>>>(pred);
    kernelC<<<NB, TPB, SMEM_C>>>(pred, offs, out);
}